// round 2
// baseline (speedup 1.0000x reference)
#include <cuda_runtime.h>
#include <cuda_bf16.h>

// DamerauLevenshtein: 32 query strings (BSZ=2 x SEQ=16, maxlen 14, argmax-derived
// "length") vs 10000 words. Full DL DP with transpositions per (b,s,w) pair.
// One thread per pair; 16x16 DP matrix as uint8 in shared memory with a
// conflict-free chunked-byte interleave (element e of thread t at word
// (e>>2)*T + t, byte e&3 -> every lane always hits its own bank).

#define T 128          // threads per block
#define ML 14          // max word / query length

__device__ __forceinline__ int eoff(int e) {
    // byte offset (from this thread's base = sd + tid*4) of matrix element e
    return ((e & ~3) << 7) + (e & 3);   // (e>>2)*T*4 + (e&3), T=128
}

__global__ __launch_bounds__(T, 4)
void dl_kernel(const int* __restrict__ x,
               const int* __restrict__ words,
               const int* __restrict__ wlen,
               float* __restrict__ out,
               int n_words)
{
    __shared__ unsigned char sd[256 * T];   // 32 KB: 256 bytes per thread
    const int tid = threadIdx.x;
    const int bs  = blockIdx.y;                 // b*SEQ + s
    const int w   = blockIdx.x * T + tid;
    const int wr  = (w < n_words) ? w : 0;      // clamp for safe loads

    unsigned char* base = sd + tid * 4;

    // ---- load query string (15 ints, broadcast across block) ----
    int xq[ML + 1];
    const int* xp = x + bs * (ML + 1);
#pragma unroll
    for (int t = 0; t <= ML; t++) xq[t] = xp[t];

    // swl = argmax (first occurrence of max)
    int swl = 0, best = xq[0];
#pragma unroll
    for (int t = 1; t <= ML; t++)
        if (xq[t] > best) { best = xq[t]; swl = t; }

    // ---- load word ----
    int wch[ML];
    const int* wp = words + wr * ML;
#pragma unroll
    for (int t = 0; t < ML; t++) wch[t] = wp[t];
    const int wl = wlen[wr];
    const int md = swl + wl;                    // max_dist

    // ---- init shared matrix rows 0 and 1 (cols 0..15) ----
#pragma unroll
    for (int jj = 0; jj < 16; jj++) base[eoff(jj)] = (unsigned char)md;   // row 0
    base[eoff(16 + 0)] = (unsigned char)md;                                // d[1][0]
    base[eoff(16 + 1)] = 0;                                                // d[1][1]
#pragma unroll
    for (int jj = 2; jj < 16; jj++) {
        int v = (jj - 1 <= wl) ? (jj - 1) : 0;                             // wla
        base[eoff(16 + jj)] = (unsigned char)v;
    }

    // previous DP row in registers (indices 1..15 used); row = d[1][*]
    int row[16];
    row[1] = 0;
#pragma unroll
    for (int jj = 2; jj < 16; jj++) row[jj] = (jj - 1 <= wl) ? (jj - 1) : 0;

    // kreg[j-1] == da[word_char_j] : last outer index i' < i with x[i'-1]==wch[j-1]
    int kreg[ML];
#pragma unroll
    for (int t = 0; t < ML; t++) kreg[t] = 0;

    for (int i = 1; i <= ML; i++) {
        const int xc = xq[i - 1];
        int db = 0;
        int prev_old = row[1];                  // old d[i][1]
        const int b1 = (i <= swl) ? i : 0;      // swl_row boundary d[i+1][1]
        row[1] = b1;
        unsigned char* rp = base + ((i + 1) << 11);   // row (i+1) base in smem
        rp[0] = (unsigned char)md;              // d[i+1][0]
        rp[1] = (unsigned char)b1;              // d[i+1][1]

#pragma unroll
        for (int j = 1; j <= ML; j++) {
            const int wc2 = wch[j - 1];
            const int k   = kreg[j - 1];
            const int l   = db;
            // transposition read d[k][l] (dynamic, conflict-free layout)
            const int dtr = (int)base[(k << 11) + ((l & ~3) << 7) + (l & 3)];
            const bool eq  = (xc == wc2);
            const int cost = eq ? 0 : 1;
            if (eq) { db = j; kreg[j - 1] = i; }   // da/db updates (post-read)

            const int up = row[j + 1];             // old d[i][j+1]
            int v = up + 1;                        // deletion
            v = min(v, row[j] + 1);                // insertion (new d[i+1][j])
            v = min(v, prev_old + cost);           // substitution (old d[i][j])
            v = min(v, dtr + (i + j - 1) - k - l); // transposition
            prev_old = up;
            row[j + 1] = v;
            // store d[i+1][j+1] (static per-j offset within the row)
            rp[(((j + 1) & ~3) << 7) + ((j + 1) & 3)] = (unsigned char)v;
        }
    }

    if (w < n_words) {
        const int e = ((swl + 1) << 4) + (wl + 1);
        out[bs * n_words + w] = (float)base[eoff(e)];
    }
}

extern "C" void kernel_launch(void* const* d_in, const int* in_sizes, int n_in,
                              void* d_out, int out_size)
{
    const int* x     = (const int*)d_in[0];      // (BSZ, SEQ, 15) int32
    const int* words = (const int*)d_in[1];      // (N, 14) int32
    const int* wlen  = (const int*)d_in[2];      // (N,) int32
    const int n_words  = in_sizes[2];
    const int bs_total = in_sizes[0] / (ML + 1); // BSZ*SEQ = 32

    dim3 grid((n_words + T - 1) / T, bs_total);
    dl_kernel<<<grid, T>>>(x, words, wlen, (float*)d_out, n_words);
}

// round 9
// speedup vs baseline: 1.0580x; 1.0580x over previous
#include <cuda_runtime.h>
#include <cuda_bf16.h>

// DamerauLevenshtein: 32 queries (BSZ*SEQ, maxlen 14) vs 10000 words.
// One thread per (b,s,word); 16x16 uint8 DP matrix in smem, chunked-byte
// interleave -> lane-private banks for the dynamic transposition read.
// R5: (a) outer loop truncated at i <= swl (block-uniform), (b) words
// counting-sorted by length on device so wl is warp-uniform and the inner
// loop truncates at the warp max length. Both cuts verified against the
// reference dependency structure (cell (i+1,j+1) reads rows <= i+1 at
// columns <= j+1 only; da/db at j > wl never influence columns <= wl+1).

#define T 128          // threads per block
#define ML 14          // max word / query length

__device__ int g_hist[16];     // zero at load; scan re-zeros for replays
__device__ int g_offs[16];
__device__ int g_perm[10240];  // sorted-position -> original word index

__global__ void hist_kernel(const int* __restrict__ wlen, int n) {
    int i = blockIdx.x * blockDim.x + threadIdx.x;
    if (i < n) atomicAdd(&g_hist[wlen[i]], 1);
}

__global__ void scan_kernel() {
    if (threadIdx.x == 0) {
        int acc = 0;
#pragma unroll
        for (int l = 0; l < 16; l++) {
            g_offs[l] = acc;
            acc += g_hist[l];
            g_hist[l] = 0;     // leave zeroed for the next graph replay
        }
    }
}

__global__ void scatter_kernel(const int* __restrict__ wlen, int n) {
    int i = blockIdx.x * blockDim.x + threadIdx.x;
    if (i < n) {
        int p = atomicAdd(&g_offs[wlen[i]], 1);
        g_perm[p] = i;         // tie order within a bin is irrelevant to d_out
    }
}

__device__ __forceinline__ int eoff(int e) {
    // byte offset (from this thread's base = sd + tid*4) of matrix element e
    return ((e & ~3) << 7) + (e & 3);   // (e>>2)*T*4 + (e&3), T=128
}

__global__ __launch_bounds__(T, 6)
void dl_kernel(const int* __restrict__ x,
               const int* __restrict__ words,
               const int* __restrict__ wlen,
               float* __restrict__ out,
               int n_words)
{
    __shared__ unsigned char sd[256 * T];   // 32 KB: 256 bytes per thread
    const int tid = threadIdx.x;
    const int bs  = blockIdx.y;                 // b*SEQ + s
    const int ws  = blockIdx.x * T + tid;       // sorted position
    const int wsr = (ws < n_words) ? ws : 0;
    const int orig = g_perm[wsr];               // original word index

    unsigned char* base = sd + tid * 4;

    // ---- load query string (15 ints, broadcast across block) ----
    int xq[ML + 1];
    const int* xp = x + bs * (ML + 1);
#pragma unroll
    for (int t = 0; t <= ML; t++) xq[t] = xp[t];

    // swl = argmax (first occurrence of max) -- uniform across the block
    int swl = 0, best = xq[0];
#pragma unroll
    for (int t = 1; t <= ML; t++)
        if (xq[t] > best) { best = xq[t]; swl = t; }

    // ---- load word (gather through the permutation; tiny, L2-resident) ----
    int wch[ML];
    const int* wp = words + orig * ML;
#pragma unroll
    for (int t = 0; t < ML; t++) wch[t] = wp[t];
    const int wl  = wlen[orig];
    const int wlm = __reduce_max_sync(0xffffffffu, wl);  // warp-uniform bound
    const int md  = swl + wl;                   // max_dist

    // ---- init shared matrix rows 0 and 1 (cols 0..15) ----
#pragma unroll
    for (int jj = 0; jj < 16; jj++) base[eoff(jj)] = (unsigned char)md;   // row 0
    base[eoff(16 + 0)] = (unsigned char)md;                                // d[1][0]
    base[eoff(16 + 1)] = 0;                                                // d[1][1]
#pragma unroll
    for (int jj = 2; jj < 16; jj++) {
        int v = (jj - 1 <= wl) ? (jj - 1) : 0;                             // wla
        base[eoff(16 + jj)] = (unsigned char)v;
    }

    // previous DP row in registers (indices 1..15 used); row = d[1][*]
    int row[16];
    row[1] = 0;
#pragma unroll
    for (int jj = 2; jj < 16; jj++) row[jj] = (jj - 1 <= wl) ? (jj - 1) : 0;

    // kreg[j-1] == da[word_char_j] : last i' < i with x[i'-1]==wch[j-1]
    int kreg[ML];
#pragma unroll
    for (int t = 0; t < ML; t++) kreg[t] = 0;

    // Rows i <= swl only (output row swl+1 written at i = swl; swl uniform).
    for (int i = 1; i <= swl; i++) {
        const int xc = xq[i - 1];
        int db = 0;
        int prev_old = row[1];                  // old d[i][1]
        const int b1 = i;                       // swl_row boundary (i <= swl here)
        row[1] = b1;
        unsigned char* rp = base + ((i + 1) << 11);   // row (i+1) base in smem
        rp[0] = (unsigned char)md;              // d[i+1][0]
        rp[1] = (unsigned char)b1;              // d[i+1][1]

#pragma unroll
        for (int j = 1; j <= ML; j++) {
            if (j > wlm) break;                 // warp-uniform column cut
            const int wc2 = wch[j - 1];
            const int k   = kreg[j - 1];
            const int l   = db;
            // transposition read d[k][l] (dynamic, conflict-free layout)
            const int dtr = (int)base[(k << 11) + ((l & ~3) << 7) + (l & 3)];
            const bool eq  = (xc == wc2);
            const int cost = eq ? 0 : 1;
            if (eq) { db = j; kreg[j - 1] = i; }   // da/db updates (post-read)

            const int up = row[j + 1];             // old d[i][j+1]
            int v = up + 1;                        // deletion
            v = min(v, row[j] + 1);                // insertion (new d[i+1][j])
            v = min(v, prev_old + cost);           // substitution (old d[i][j])
            v = min(v, dtr + (i + j - 1) - k - l); // transposition
            prev_old = up;
            row[j + 1] = v;
            // store d[i+1][j+1] (static per-j offset within the row)
            rp[(((j + 1) & ~3) << 7) + ((j + 1) & 3)] = (unsigned char)v;
        }
    }

    if (ws < n_words) {
        const int e = ((swl + 1) << 4) + (wl + 1);
        out[bs * n_words + orig] = (float)base[eoff(e)];
    }
}

extern "C" void kernel_launch(void* const* d_in, const int* in_sizes, int n_in,
                              void* d_out, int out_size)
{
    const int* x     = (const int*)d_in[0];      // (BSZ, SEQ, 15) int32
    const int* words = (const int*)d_in[1];      // (N, 14) int32
    const int* wlen  = (const int*)d_in[2];      // (N,) int32
    const int n_words  = in_sizes[2];
    const int bs_total = in_sizes[0] / (ML + 1); // BSZ*SEQ = 32

    int nb = (n_words + 255) / 256;
    hist_kernel<<<nb, 256>>>(wlen, n_words);
    scan_kernel<<<1, 32>>>();
    scatter_kernel<<<nb, 256>>>(wlen, n_words);

    dim3 grid((n_words + T - 1) / T, bs_total);
    dl_kernel<<<grid, T>>>(x, words, wlen, (float*)d_out, n_words);
}